// round 12
// baseline (speedup 1.0000x reference)
#include <cuda_runtime.h>
#include <cuda_fp16.h>

// Problem constants (fixed by the dataset)
#define NMAX 50048
#define EMAX 1600000
#define WDIM 64
#define HDIM 128

// Scratch (allocation-free rule: __device__ globals)
__device__ __half gA[NMAX * HDIM];     // x @ w1[0:64,:]  + b1
__device__ __half gB[NMAX * HDIM];     // x @ w1[64:128,:]
__device__ int    gCnt[NMAX];          // per-dst edge count
__device__ int    gOff[NMAX + 1];      // exclusive prefix (bin starts)
__device__ int    gCursor[NMAX];       // scatter cursors
__device__ int2   gSortedE[EMAX];      // {src, orig_e} grouped by dst
__device__ float  gEsort[EMAX];        // exp(logit) in sorted order
// decoupled-lookback scan state (flags reset by hist_kernel each call)
__device__ volatile int gBlockSum[256];
__device__ volatile int gBlockFlag[256];

// ---------------------------------------------------------------------------
// Kernel 1: per-node precompute  A[n][j] = sum_k x[n][k]*w1[k][j] + b1[j]
//                                B[n][j] = sum_k x[n][k]*w1[64+k][j]
// ---------------------------------------------------------------------------
#define TR 16
__global__ void precompute_ab(const float* __restrict__ x,
                              const float* __restrict__ w1,
                              const float* __restrict__ b1, int N) {
    __shared__ float xs[TR][WDIM];
    const int row0 = blockIdx.x * TR;
    const int tid  = threadIdx.x;

    for (int i = tid; i < TR * WDIM; i += 256) {
        int r = i >> 6, k = i & 63;
        int gr = row0 + r;
        xs[r][k] = (gr < N) ? x[gr * WDIM + k] : 0.0f;
    }
    __syncthreads();

    const int col  = tid & 127;
    const int half = tid >> 7;   // 0 -> A, 1 -> B
    const float* wbase = w1 + half * WDIM * HDIM + col;

    float acc[TR];
#pragma unroll
    for (int r = 0; r < TR; r++) acc[r] = 0.0f;

#pragma unroll 8
    for (int k = 0; k < WDIM; k++) {
        float w = __ldg(wbase + k * HDIM);
#pragma unroll
        for (int r = 0; r < TR; r++) acc[r] += xs[r][k] * w;
    }

    const float bias = (half == 0) ? __ldg(&b1[col]) : 0.0f;
    __half* out = (half == 0) ? gA : gB;
#pragma unroll
    for (int r = 0; r < TR; r++) {
        int gr = row0 + r;
        if (gr < N) out[gr * HDIM + col] = __float2half_rn(acc[r] + bias);
    }
}

// ---------------------------------------------------------------------------
// Kernel 2: histogram of dst (2 edges per thread). Block 0 also resets the
// scan flags for this call (scan launches after hist completes).
// ---------------------------------------------------------------------------
__global__ void hist_kernel(const int* __restrict__ dst, int E) {
    if (blockIdx.x == 0 && threadIdx.x < 256) {
        gBlockFlag[threadIdx.x] = 0;
    }
    int t = blockIdx.x * blockDim.x + threadIdx.x;
    int e0 = t * 2;
    if (e0 + 1 < E) {
        int2 d2 = reinterpret_cast<const int2*>(dst)[t];
        atomicAdd(&gCnt[d2.x], 1);
        atomicAdd(&gCnt[d2.y], 1);
    } else if (e0 < E) {
        atomicAdd(&gCnt[dst[e0]], 1);
    }
}

// ---------------------------------------------------------------------------
// Kernel 3: single-pass scan with lookback. 196 blocks (all co-resident on
// 148 SMs -> spin is deadlock-free). Produces gOff / gCursor.
// ---------------------------------------------------------------------------
__global__ void scan_onepass(int N, int E) {
    __shared__ int sh[256];
    __shared__ int exclBase;
    const int bid = blockIdx.x;
    const int tid = threadIdx.x;
    const int idx = bid * 256 + tid;

    int v = (idx < N) ? gCnt[idx] : 0;
    sh[tid] = v;
    __syncthreads();
#pragma unroll
    for (int o = 1; o < 256; o <<= 1) {
        int t = (tid >= o) ? sh[tid - o] : 0;
        __syncthreads();
        sh[tid] += t;
        __syncthreads();
    }
    const int incl = sh[tid];          // inclusive within block

    if (tid == 255) {                  // publish block aggregate
        gBlockSum[bid] = incl;
        __threadfence();
        gBlockFlag[bid] = 1;
    }
    if (tid == 0) {
        int s = 0;
        for (int p = 0; p < bid; p++) {
            while (gBlockFlag[p] == 0) { }
            s += gBlockSum[p];
        }
        exclBase = s;
    }
    __syncthreads();

    const int excl = exclBase + incl - v;
    if (idx < N) {
        gOff[idx]    = excl;
        gCursor[idx] = excl;
        if (idx == N - 1) gOff[N] = excl + v;   // == E
    }
}

// ---------------------------------------------------------------------------
// Kernel 4: scatter edges into dst-grouped order (2 edges/thread)
// ---------------------------------------------------------------------------
__global__ void scatter_kernel(const int* __restrict__ src,
                               const int* __restrict__ dst, int E) {
    int t = blockIdx.x * blockDim.x + threadIdx.x;
    int e0 = t * 2;
    if (e0 + 1 < E) {
        int2 s2 = reinterpret_cast<const int2*>(src)[t];
        int2 d2 = reinterpret_cast<const int2*>(dst)[t];
        int p0 = atomicAdd(&gCursor[d2.x], 1);
        gSortedE[p0] = make_int2(s2.x, e0);
        int p1 = atomicAdd(&gCursor[d2.y], 1);
        gSortedE[p1] = make_int2(s2.y, e0 + 1);
    } else if (e0 < E) {
        int d = dst[e0];
        int pos = atomicAdd(&gCursor[d], 1);
        gSortedE[pos] = make_int2(src[e0], e0);
    }
}

// ---------------------------------------------------------------------------
// Kernel 5: FUSED per-node kernel — warp per node, no atomics.
// 8 lanes/edge, contiguous subgroup addressing (1 full 128B line per LDG per
// subgroup). launch_bounds(256,3): cap ~85 regs -> 3 blocks/SM = 24 warps
// for latency hiding of the random L2 gathers.
// ---------------------------------------------------------------------------
__global__ void __launch_bounds__(256, 3) fused_node(
        const float* __restrict__ y,
        const float* __restrict__ w2,
        const float* __restrict__ b2,
        float* __restrict__ alpha_out,
        float* __restrict__ yhat, int N) {
    const int lane = threadIdx.x & 31;
    const int sub  = lane & 7;          // lane within 8-group
    const int g    = lane >> 3;         // subgroup 0..3
    const int node = blockIdx.x * (blockDim.x >> 5) + (threadIdx.x >> 5);
    if (node >= N) return;

    const int start = gOff[node];
    const int end   = gOff[node + 1];

    const uint4* A4 = reinterpret_cast<const uint4*>(gA);  // 16 uint4 / row
    const uint4* B4 = reinterpret_cast<const uint4*>(gB);

    // B[node]: lane sub holds halves [8*sub, 8*sub+8) and [64+8*sub, ...+8)
    uint4 br0 = B4[node * 16 + sub];
    uint4 br1 = B4[node * 16 + 8 + sub];
    __half2 bh0[4], bh1[4];
    {
        const __half2* p0 = reinterpret_cast<const __half2*>(&br0);
        const __half2* p1 = reinterpret_cast<const __half2*>(&br1);
#pragma unroll
        for (int i = 0; i < 4; i++) { bh0[i] = p0[i]; bh1[i] = p1[i]; }
    }

    // w2 coefficients matching the halves above
    float w2a[8], w2b[8];
#pragma unroll
    for (int i = 0; i < 2; i++) {
        float4 ta = reinterpret_cast<const float4*>(w2)[sub * 2 + i];
        float4 tb = reinterpret_cast<const float4*>(w2)[16 + sub * 2 + i];
        w2a[4 * i] = ta.x; w2a[4 * i + 1] = ta.y; w2a[4 * i + 2] = ta.z; w2a[4 * i + 3] = ta.w;
        w2b[4 * i] = tb.x; w2b[4 * i + 1] = tb.y; w2b[4 * i + 2] = tb.z; w2b[4 * i + 3] = tb.w;
    }
    const float  b2v = __ldg(b2);
    const __half2 z2 = __float2half2_rn(0.0f);

    float denom_part = 0.0f;

    for (int base = start; base < end; base += 16) {
        int  e[4]; bool v[4]; int s[4];
#pragma unroll
        for (int j = 0; j < 4; j++) {
            e[j] = base + g + 4 * j;
            v[j] = e[j] < end;
            s[j] = v[j] ? gSortedE[e[j]].x : 0;   // broadcast within subgroup
        }
        // 8 independent, fully-coalesced gathers issued before any use
        uint4 a0[4], a1[4];
#pragma unroll
        for (int j = 0; j < 4; j++) {
            a0[j] = A4[s[j] * 16 + sub];
            a1[j] = A4[s[j] * 16 + 8 + sub];
        }

        float p[4];
#pragma unroll
        for (int j = 0; j < 4; j++) {
            const __half2* q0 = reinterpret_cast<const __half2*>(&a0[j]);
            const __half2* q1 = reinterpret_cast<const __half2*>(&a1[j]);
            float acc = 0.0f;
#pragma unroll
            for (int i = 0; i < 4; i++) {
                float2 f;
                f = __half22float2(__hmax2(__hadd2(q0[i], bh0[i]), z2));
                acc = fmaf(f.x, w2a[2 * i], fmaf(f.y, w2a[2 * i + 1], acc));
                f = __half22float2(__hmax2(__hadd2(q1[i], bh1[i]), z2));
                acc = fmaf(f.x, w2b[2 * i], fmaf(f.y, w2b[2 * i + 1], acc));
            }
            p[j] = acc;
        }
        // 4 interleaved 3-step subgroup reductions
#pragma unroll
        for (int o = 4; o > 0; o >>= 1) {
#pragma unroll
            for (int j = 0; j < 4; j++)
                p[j] += __shfl_xor_sync(0xFFFFFFFFu, p[j], o);
        }
        if (sub == 0) {
#pragma unroll
            for (int j = 0; j < 4; j++) {
                if (v[j]) {
                    float ev = __expf(p[j] + b2v);
                    gEsort[e[j]] = ev;
                    denom_part += ev;
                }
            }
        }
    }

    // total denom over the warp (only sub==0 lanes carry partials)
#pragma unroll
    for (int o = 16; o > 0; o >>= 1)
        denom_part += __shfl_xor_sync(0xFFFFFFFFu, denom_part, o);
    const float inv = 1.0f / denom_part;

    // pass 2: alpha + weighted sum, coalesced over the node's segment
    float sum = 0.0f;
    for (int i = start + lane; i < end; i += 32) {
        int2  rec = gSortedE[i];
        float a   = gEsort[i] * inv;
        alpha_out[rec.y] = a;
        sum += __ldg(&y[rec.x]) * a;
    }
#pragma unroll
    for (int o = 16; o > 0; o >>= 1)
        sum += __shfl_xor_sync(0xFFFFFFFFu, sum, o);
    if (lane == 0) yhat[node] = sum;
}

// ---------------------------------------------------------------------------
extern "C" void kernel_launch(void* const* d_in, const int* in_sizes, int n_in,
                              void* d_out, int out_size) {
    const float* x  = (const float*)d_in[0];
    const float* y  = (const float*)d_in[1];
    const int*   ei = (const int*)  d_in[2];
    const float* w1 = (const float*)d_in[3];
    const float* b1 = (const float*)d_in[4];
    const float* w2 = (const float*)d_in[5];
    const float* b2 = (const float*)d_in[6];

    const int N = in_sizes[1];        // y has N elements
    const int E = in_sizes[2] / 2;    // edge_index is [2, E]

    float* yhat  = (float*)d_out;         // first N elements
    float* alpha = (float*)d_out + N;     // next E elements

    const int* src = ei;
    const int* dst = ei + E;

    const int scanBlocks = (N + 255) / 256;   // 196 <= 256

    // zero histogram via async memset (capturable, no extra kernel)
    void* cntPtr = nullptr;
    cudaGetSymbolAddress(&cntPtr, gCnt);
    cudaMemsetAsync(cntPtr, 0, N * sizeof(int));

    precompute_ab<<<(N + TR - 1) / TR, 256>>>(x, w1, b1, N);
    hist_kernel<<<(E / 2 + 255) / 256, 256>>>(dst, E);
    scan_onepass<<<scanBlocks, 256>>>(N, E);
    scatter_kernel<<<(E / 2 + 255) / 256, 256>>>(src, dst, E);
    fused_node<<<(N + 7) / 8, 256>>>(y, w2, b2, alpha, yhat, N);
}

// round 13
// speedup vs baseline: 1.4027x; 1.4027x over previous
#include <cuda_runtime.h>
#include <cuda_fp16.h>

// Problem constants (fixed by the dataset)
#define NMAX 50048
#define EMAX 1600000
#define WDIM 64
#define HDIM 128

// Scratch (allocation-free rule: __device__ globals)
__device__ __half gA[NMAX * HDIM];     // x @ w1[0:64,:]  + b1
__device__ __half gB[NMAX * HDIM];     // x @ w1[64:128,:]
__device__ int    gCnt[NMAX];          // per-dst edge count
__device__ int    gOff[NMAX + 1];      // exclusive prefix (bin starts)
__device__ int    gCursor[NMAX];       // scatter cursors
__device__ int2   gSortedE[EMAX];      // {src, orig_e} grouped by dst
__device__ float  gEsort[EMAX];        // exp(logit) in sorted order
// decoupled-lookback scan state (flags reset by hist_kernel each call)
__device__ volatile int gBlockSum[256];
__device__ volatile int gBlockFlag[256];

// ---------------------------------------------------------------------------
// Kernel 1: per-node precompute  A[n][j] = sum_k x[n][k]*w1[k][j] + b1[j]
//                                B[n][j] = sum_k x[n][k]*w1[64+k][j]
// ---------------------------------------------------------------------------
#define TR 16
__global__ void precompute_ab(const float* __restrict__ x,
                              const float* __restrict__ w1,
                              const float* __restrict__ b1, int N) {
    __shared__ float xs[TR][WDIM];
    const int row0 = blockIdx.x * TR;
    const int tid  = threadIdx.x;

    for (int i = tid; i < TR * WDIM; i += 256) {
        int r = i >> 6, k = i & 63;
        int gr = row0 + r;
        xs[r][k] = (gr < N) ? x[gr * WDIM + k] : 0.0f;
    }
    __syncthreads();

    const int col  = tid & 127;
    const int half = tid >> 7;   // 0 -> A, 1 -> B
    const float* wbase = w1 + half * WDIM * HDIM + col;

    float acc[TR];
#pragma unroll
    for (int r = 0; r < TR; r++) acc[r] = 0.0f;

#pragma unroll 8
    for (int k = 0; k < WDIM; k++) {
        float w = __ldg(wbase + k * HDIM);
#pragma unroll
        for (int r = 0; r < TR; r++) acc[r] += xs[r][k] * w;
    }

    const float bias = (half == 0) ? __ldg(&b1[col]) : 0.0f;
    __half* out = (half == 0) ? gA : gB;
#pragma unroll
    for (int r = 0; r < TR; r++) {
        int gr = row0 + r;
        if (gr < N) out[gr * HDIM + col] = __float2half_rn(acc[r] + bias);
    }
}

// ---------------------------------------------------------------------------
// Kernel 2: histogram of dst (2 edges per thread). Block 0 also resets the
// scan flags for this call (scan launches after hist completes).
// ---------------------------------------------------------------------------
__global__ void hist_kernel(const int* __restrict__ dst, int E) {
    if (blockIdx.x == 0 && threadIdx.x < 256) {
        gBlockFlag[threadIdx.x] = 0;
    }
    int t = blockIdx.x * blockDim.x + threadIdx.x;
    int e0 = t * 2;
    if (e0 + 1 < E) {
        int2 d2 = reinterpret_cast<const int2*>(dst)[t];
        atomicAdd(&gCnt[d2.x], 1);
        atomicAdd(&gCnt[d2.y], 1);
    } else if (e0 < E) {
        atomicAdd(&gCnt[dst[e0]], 1);
    }
}

// ---------------------------------------------------------------------------
// Kernel 3: single-pass scan, PARALLEL lookback: lane t waits on flag t,
// then block-reduces the prefix. 196 blocks, all co-resident.
// ---------------------------------------------------------------------------
__global__ void scan_onepass(int N, int E) {
    __shared__ int sh[256];
    __shared__ int pre[256];
    const int bid = blockIdx.x;
    const int tid = threadIdx.x;
    const int idx = bid * 256 + tid;

    int v = (idx < N) ? gCnt[idx] : 0;
    sh[tid] = v;
    __syncthreads();
#pragma unroll
    for (int o = 1; o < 256; o <<= 1) {
        int t = (tid >= o) ? sh[tid - o] : 0;
        __syncthreads();
        sh[tid] += t;
        __syncthreads();
    }
    const int incl = sh[tid];          // inclusive within block

    if (tid == 255) {                  // publish block aggregate
        gBlockSum[bid] = incl;
        __threadfence();
        gBlockFlag[bid] = 1;
    }
    // parallel lookback: lane t grabs predecessor t's aggregate
    int contrib = 0;
    if (tid < bid) {
        while (gBlockFlag[tid] == 0) { }
        contrib = gBlockSum[tid];
    }
    pre[tid] = contrib;
    __syncthreads();
    for (int o = 128; o > 0; o >>= 1) {
        if (tid < o) pre[tid] += pre[tid + o];
        __syncthreads();
    }
    const int excl = pre[0] + incl - v;
    if (idx < N) {
        gOff[idx]    = excl;
        gCursor[idx] = excl;
        if (idx == N - 1) gOff[N] = excl + v;   // == E
    }
}

// ---------------------------------------------------------------------------
// Kernel 4: scatter edges into dst-grouped order (2 edges/thread)
// ---------------------------------------------------------------------------
__global__ void scatter_kernel(const int* __restrict__ src,
                               const int* __restrict__ dst, int E) {
    int t = blockIdx.x * blockDim.x + threadIdx.x;
    int e0 = t * 2;
    if (e0 + 1 < E) {
        int2 s2 = reinterpret_cast<const int2*>(src)[t];
        int2 d2 = reinterpret_cast<const int2*>(dst)[t];
        int p0 = atomicAdd(&gCursor[d2.x], 1);
        gSortedE[p0] = make_int2(s2.x, e0);
        int p1 = atomicAdd(&gCursor[d2.y], 1);
        gSortedE[p1] = make_int2(s2.y, e0 + 1);
    } else if (e0 < E) {
        int d = dst[e0];
        int pos = atomicAdd(&gCursor[d], 1);
        gSortedE[pos] = make_int2(src[e0], e0);
    }
}

// ---------------------------------------------------------------------------
// Kernel 5: FUSED per-node kernel — warp per node, no atomics.
// 8 lanes/edge, contiguous addressing (1 full 128B line per subgroup LDG).
// 2 edges per subgroup per iter (8/warp) -> ~70 live regs: fits the
// (256,3) cap WITHOUT spilling -> 3 blocks/SM = 24 warps latency hiding.
// ---------------------------------------------------------------------------
__global__ void __launch_bounds__(256, 3) fused_node(
        const float* __restrict__ y,
        const float* __restrict__ w2,
        const float* __restrict__ b2,
        float* __restrict__ alpha_out,
        float* __restrict__ yhat, int N) {
    const int lane = threadIdx.x & 31;
    const int sub  = lane & 7;          // lane within 8-group
    const int g    = lane >> 3;         // subgroup 0..3
    const int node = blockIdx.x * (blockDim.x >> 5) + (threadIdx.x >> 5);
    if (node >= N) return;

    const int start = gOff[node];
    const int end   = gOff[node + 1];

    const uint4* A4 = reinterpret_cast<const uint4*>(gA);  // 16 uint4 / row
    const uint4* B4 = reinterpret_cast<const uint4*>(gB);

    // B[node]: lane sub holds halves [8*sub, 8*sub+8) and [64+8*sub, ...+8)
    uint4 br0 = B4[node * 16 + sub];
    uint4 br1 = B4[node * 16 + 8 + sub];
    __half2 bh0[4], bh1[4];
    {
        const __half2* p0 = reinterpret_cast<const __half2*>(&br0);
        const __half2* p1 = reinterpret_cast<const __half2*>(&br1);
#pragma unroll
        for (int i = 0; i < 4; i++) { bh0[i] = p0[i]; bh1[i] = p1[i]; }
    }

    // w2 coefficients matching the halves above
    float w2a[8], w2b[8];
#pragma unroll
    for (int i = 0; i < 2; i++) {
        float4 ta = reinterpret_cast<const float4*>(w2)[sub * 2 + i];
        float4 tb = reinterpret_cast<const float4*>(w2)[16 + sub * 2 + i];
        w2a[4 * i] = ta.x; w2a[4 * i + 1] = ta.y; w2a[4 * i + 2] = ta.z; w2a[4 * i + 3] = ta.w;
        w2b[4 * i] = tb.x; w2b[4 * i + 1] = tb.y; w2b[4 * i + 2] = tb.z; w2b[4 * i + 3] = tb.w;
    }
    const float  b2v = __ldg(b2);
    const __half2 z2 = __float2half2_rn(0.0f);

    float denom_part = 0.0f;

    for (int base = start; base < end; base += 8) {
        const int e0 = base + g, e1 = base + g + 4;
        const bool v0 = e0 < end, v1 = e1 < end;
        const int s0 = v0 ? gSortedE[e0].x : 0;  // broadcast within subgroup
        const int s1 = v1 ? gSortedE[e1].x : 0;

        // 4 independent, fully-coalesced gathers issued before any use
        uint4 a00 = A4[s0 * 16 + sub];
        uint4 a01 = A4[s0 * 16 + 8 + sub];
        uint4 a10 = A4[s1 * 16 + sub];
        uint4 a11 = A4[s1 * 16 + 8 + sub];

        float p0 = 0.0f, p1 = 0.0f;
        {
            const __half2* q0 = reinterpret_cast<const __half2*>(&a00);
            const __half2* q1 = reinterpret_cast<const __half2*>(&a01);
            const __half2* r0 = reinterpret_cast<const __half2*>(&a10);
            const __half2* r1 = reinterpret_cast<const __half2*>(&a11);
#pragma unroll
            for (int i = 0; i < 4; i++) {
                float2 f;
                f = __half22float2(__hmax2(__hadd2(q0[i], bh0[i]), z2));
                p0 = fmaf(f.x, w2a[2 * i], fmaf(f.y, w2a[2 * i + 1], p0));
                f = __half22float2(__hmax2(__hadd2(q1[i], bh1[i]), z2));
                p0 = fmaf(f.x, w2b[2 * i], fmaf(f.y, w2b[2 * i + 1], p0));
                f = __half22float2(__hmax2(__hadd2(r0[i], bh0[i]), z2));
                p1 = fmaf(f.x, w2a[2 * i], fmaf(f.y, w2a[2 * i + 1], p1));
                f = __half22float2(__hmax2(__hadd2(r1[i], bh1[i]), z2));
                p1 = fmaf(f.x, w2b[2 * i], fmaf(f.y, w2b[2 * i + 1], p1));
            }
        }
        // two interleaved 3-step subgroup reductions
#pragma unroll
        for (int o = 4; o > 0; o >>= 1) {
            p0 += __shfl_xor_sync(0xFFFFFFFFu, p0, o);
            p1 += __shfl_xor_sync(0xFFFFFFFFu, p1, o);
        }
        if (sub == 0) {
            if (v0) { float ev = __expf(p0 + b2v); gEsort[e0] = ev; denom_part += ev; }
            if (v1) { float ev = __expf(p1 + b2v); gEsort[e1] = ev; denom_part += ev; }
        }
    }

    // total denom over the warp (only sub==0 lanes carry partials)
#pragma unroll
    for (int o = 16; o > 0; o >>= 1)
        denom_part += __shfl_xor_sync(0xFFFFFFFFu, denom_part, o);
    const float inv = 1.0f / denom_part;

    // pass 2: alpha + weighted sum, coalesced over the node's segment
    float sum = 0.0f;
    for (int i = start + lane; i < end; i += 32) {
        int2  rec = gSortedE[i];
        float a   = gEsort[i] * inv;
        alpha_out[rec.y] = a;
        sum += __ldg(&y[rec.x]) * a;
    }
#pragma unroll
    for (int o = 16; o > 0; o >>= 1)
        sum += __shfl_xor_sync(0xFFFFFFFFu, sum, o);
    if (lane == 0) yhat[node] = sum;
}

// ---------------------------------------------------------------------------
extern "C" void kernel_launch(void* const* d_in, const int* in_sizes, int n_in,
                              void* d_out, int out_size) {
    const float* x  = (const float*)d_in[0];
    const float* y  = (const float*)d_in[1];
    const int*   ei = (const int*)  d_in[2];
    const float* w1 = (const float*)d_in[3];
    const float* b1 = (const float*)d_in[4];
    const float* w2 = (const float*)d_in[5];
    const float* b2 = (const float*)d_in[6];

    const int N = in_sizes[1];        // y has N elements
    const int E = in_sizes[2] / 2;    // edge_index is [2, E]

    float* yhat  = (float*)d_out;         // first N elements
    float* alpha = (float*)d_out + N;     // next E elements

    const int* src = ei;
    const int* dst = ei + E;

    const int scanBlocks = (N + 255) / 256;   // 196 <= 256

    // zero histogram via async memset (capturable, no extra kernel)
    void* cntPtr = nullptr;
    cudaGetSymbolAddress(&cntPtr, gCnt);
    cudaMemsetAsync(cntPtr, 0, N * sizeof(int));

    precompute_ab<<<(N + TR - 1) / TR, 256>>>(x, w1, b1, N);
    hist_kernel<<<(E / 2 + 255) / 256, 256>>>(dst, E);
    scan_onepass<<<scanBlocks, 256>>>(N, E);
    scatter_kernel<<<(E / 2 + 255) / 256, 256>>>(src, dst, E);
    fused_node<<<(N + 7) / 8, 256>>>(y, w2, b2, alpha, yhat, N);
}

// round 14
// speedup vs baseline: 1.4425x; 1.0283x over previous
#include <cuda_runtime.h>
#include <cuda_fp16.h>

// Problem constants (fixed by the dataset)
#define NMAX 50048
#define EMAX 1600000
#define WDIM 64
#define HDIM 128

// Scratch (allocation-free rule: __device__ globals)
__device__ __half gA[NMAX * HDIM];     // x @ w1[0:64,:]  + b1
__device__ __half gB[NMAX * HDIM];     // x @ w1[64:128,:]
__device__ int    gCnt[NMAX];          // per-dst edge count
__device__ int    gOff[NMAX + 1];      // exclusive prefix (bin starts)
__device__ int    gCursor[NMAX];       // scatter cursors
__device__ int2   gSortedE[EMAX];      // {src, orig_e} grouped by dst
__device__ float  gEsort[EMAX];        // exp(logit) in sorted order
// decoupled-lookback scan state (flags reset by hist_kernel each call)
__device__ volatile int gBlockSum[256];
__device__ volatile int gBlockFlag[256];

// ---------------------------------------------------------------------------
// Kernel 1: per-node precompute  A[n][j] = sum_k x[n][k]*w1[k][j] + b1[j]
//                                B[n][j] = sum_k x[n][k]*w1[64+k][j]
// ---------------------------------------------------------------------------
#define TR 16
__global__ void precompute_ab(const float* __restrict__ x,
                              const float* __restrict__ w1,
                              const float* __restrict__ b1, int N) {
    __shared__ float xs[TR][WDIM];
    const int row0 = blockIdx.x * TR;
    const int tid  = threadIdx.x;

    for (int i = tid; i < TR * WDIM; i += 256) {
        int r = i >> 6, k = i & 63;
        int gr = row0 + r;
        xs[r][k] = (gr < N) ? x[gr * WDIM + k] : 0.0f;
    }
    __syncthreads();

    const int col  = tid & 127;
    const int half = tid >> 7;   // 0 -> A, 1 -> B
    const float* wbase = w1 + half * WDIM * HDIM + col;

    float acc[TR];
#pragma unroll
    for (int r = 0; r < TR; r++) acc[r] = 0.0f;

#pragma unroll 8
    for (int k = 0; k < WDIM; k++) {
        float w = __ldg(wbase + k * HDIM);
#pragma unroll
        for (int r = 0; r < TR; r++) acc[r] += xs[r][k] * w;
    }

    const float bias = (half == 0) ? __ldg(&b1[col]) : 0.0f;
    __half* out = (half == 0) ? gA : gB;
#pragma unroll
    for (int r = 0; r < TR; r++) {
        int gr = row0 + r;
        if (gr < N) out[gr * HDIM + col] = __float2half_rn(acc[r] + bias);
    }
}

// ---------------------------------------------------------------------------
// Kernel 2: histogram of dst (4 edges per thread, deep atomic pipeline).
// Block 0 also resets the scan flags for this call.
// ---------------------------------------------------------------------------
__global__ void hist_kernel(const int* __restrict__ dst, int E) {
    if (blockIdx.x == 0 && threadIdx.x < 256) {
        gBlockFlag[threadIdx.x] = 0;
    }
    int t = blockIdx.x * blockDim.x + threadIdx.x;
    int e0 = t * 4;
    if (e0 + 3 < E) {
        int4 d4 = reinterpret_cast<const int4*>(dst)[t];
        atomicAdd(&gCnt[d4.x], 1);
        atomicAdd(&gCnt[d4.y], 1);
        atomicAdd(&gCnt[d4.z], 1);
        atomicAdd(&gCnt[d4.w], 1);
    } else {
        for (int e = e0; e < E; e++) atomicAdd(&gCnt[dst[e]], 1);
    }
}

// ---------------------------------------------------------------------------
// Kernel 3: single-pass scan, parallel lookback.
// ---------------------------------------------------------------------------
__global__ void scan_onepass(int N, int E) {
    __shared__ int sh[256];
    __shared__ int pre[256];
    const int bid = blockIdx.x;
    const int tid = threadIdx.x;
    const int idx = bid * 256 + tid;

    int v = (idx < N) ? gCnt[idx] : 0;
    sh[tid] = v;
    __syncthreads();
#pragma unroll
    for (int o = 1; o < 256; o <<= 1) {
        int t = (tid >= o) ? sh[tid - o] : 0;
        __syncthreads();
        sh[tid] += t;
        __syncthreads();
    }
    const int incl = sh[tid];          // inclusive within block

    if (tid == 255) {                  // publish block aggregate
        gBlockSum[bid] = incl;
        __threadfence();
        gBlockFlag[bid] = 1;
    }
    // parallel lookback: lane t grabs predecessor t's aggregate
    int contrib = 0;
    if (tid < bid) {
        while (gBlockFlag[tid] == 0) { }
        contrib = gBlockSum[tid];
    }
    pre[tid] = contrib;
    __syncthreads();
    for (int o = 128; o > 0; o >>= 1) {
        if (tid < o) pre[tid] += pre[tid + o];
        __syncthreads();
    }
    const int excl = pre[0] + incl - v;
    if (idx < N) {
        gOff[idx]    = excl;
        gCursor[idx] = excl;
        if (idx == N - 1) gOff[N] = excl + v;   // == E
    }
}

// ---------------------------------------------------------------------------
// Kernel 4: scatter edges into dst-grouped order (4 edges/thread, int4 loads,
// 4 independent ATOMG chains in flight per thread)
// ---------------------------------------------------------------------------
__global__ void scatter_kernel(const int* __restrict__ src,
                               const int* __restrict__ dst, int E) {
    int t = blockIdx.x * blockDim.x + threadIdx.x;
    int e0 = t * 4;
    if (e0 + 3 < E) {
        int4 s4 = reinterpret_cast<const int4*>(src)[t];
        int4 d4 = reinterpret_cast<const int4*>(dst)[t];
        int p0 = atomicAdd(&gCursor[d4.x], 1);
        int p1 = atomicAdd(&gCursor[d4.y], 1);
        int p2 = atomicAdd(&gCursor[d4.z], 1);
        int p3 = atomicAdd(&gCursor[d4.w], 1);
        gSortedE[p0] = make_int2(s4.x, e0);
        gSortedE[p1] = make_int2(s4.y, e0 + 1);
        gSortedE[p2] = make_int2(s4.z, e0 + 2);
        gSortedE[p3] = make_int2(s4.w, e0 + 3);
    } else {
        for (int e = e0; e < E; e++) {
            int pos = atomicAdd(&gCursor[dst[e]], 1);
            gSortedE[pos] = make_int2(src[e], e);
        }
    }
}

// ---------------------------------------------------------------------------
// Kernel 5: FUSED per-node kernel — warp per node, no atomics.
// 8 lanes/edge, contiguous addressing. Software-pipelined: next iteration's
// edge records are prefetched before computing the current batch, so the
// record-load latency overlaps the A-gather + MLP of the current 8 edges.
// ---------------------------------------------------------------------------
__global__ void __launch_bounds__(256, 3) fused_node(
        const float* __restrict__ y,
        const float* __restrict__ w2,
        const float* __restrict__ b2,
        float* __restrict__ alpha_out,
        float* __restrict__ yhat, int N) {
    const int lane = threadIdx.x & 31;
    const int sub  = lane & 7;          // lane within 8-group
    const int g    = lane >> 3;         // subgroup 0..3
    const int node = blockIdx.x * (blockDim.x >> 5) + (threadIdx.x >> 5);
    if (node >= N) return;

    const int start = gOff[node];
    const int end   = gOff[node + 1];

    const uint4* A4 = reinterpret_cast<const uint4*>(gA);  // 16 uint4 / row
    const uint4* B4 = reinterpret_cast<const uint4*>(gB);

    // B[node]: lane sub holds halves [8*sub, 8*sub+8) and [64+8*sub, ...+8)
    uint4 br0 = B4[node * 16 + sub];
    uint4 br1 = B4[node * 16 + 8 + sub];
    __half2 bh0[4], bh1[4];
    {
        const __half2* p0 = reinterpret_cast<const __half2*>(&br0);
        const __half2* p1 = reinterpret_cast<const __half2*>(&br1);
#pragma unroll
        for (int i = 0; i < 4; i++) { bh0[i] = p0[i]; bh1[i] = p1[i]; }
    }

    // w2 coefficients matching the halves above
    float w2a[8], w2b[8];
#pragma unroll
    for (int i = 0; i < 2; i++) {
        float4 ta = reinterpret_cast<const float4*>(w2)[sub * 2 + i];
        float4 tb = reinterpret_cast<const float4*>(w2)[16 + sub * 2 + i];
        w2a[4 * i] = ta.x; w2a[4 * i + 1] = ta.y; w2a[4 * i + 2] = ta.z; w2a[4 * i + 3] = ta.w;
        w2b[4 * i] = tb.x; w2b[4 * i + 1] = tb.y; w2b[4 * i + 2] = tb.z; w2b[4 * i + 3] = tb.w;
    }
    const float  b2v = __ldg(b2);
    const __half2 z2 = __float2half2_rn(0.0f);

    float denom_part = 0.0f;

    // prologue: records for the first batch
    int s0 = (start + g     < end) ? gSortedE[start + g].x     : 0;
    int s1 = (start + g + 4 < end) ? gSortedE[start + g + 4].x : 0;

    for (int base = start; base < end; base += 8) {
        const int e0 = base + g, e1 = base + g + 4;
        const bool v0 = e0 < end, v1 = e1 < end;

        // prefetch next batch's records (overlaps A-gather + compute below)
        const int n0 = e0 + 8, n1 = e1 + 8;
        const int sn0 = (n0 < end) ? gSortedE[n0].x : 0;
        const int sn1 = (n1 < end) ? gSortedE[n1].x : 0;

        // 4 independent, fully-coalesced gathers issued before any use
        uint4 a00 = A4[s0 * 16 + sub];
        uint4 a01 = A4[s0 * 16 + 8 + sub];
        uint4 a10 = A4[s1 * 16 + sub];
        uint4 a11 = A4[s1 * 16 + 8 + sub];

        float p0 = 0.0f, p1 = 0.0f;
        {
            const __half2* q0 = reinterpret_cast<const __half2*>(&a00);
            const __half2* q1 = reinterpret_cast<const __half2*>(&a01);
            const __half2* r0 = reinterpret_cast<const __half2*>(&a10);
            const __half2* r1 = reinterpret_cast<const __half2*>(&a11);
#pragma unroll
            for (int i = 0; i < 4; i++) {
                float2 f;
                f = __half22float2(__hmax2(__hadd2(q0[i], bh0[i]), z2));
                p0 = fmaf(f.x, w2a[2 * i], fmaf(f.y, w2a[2 * i + 1], p0));
                f = __half22float2(__hmax2(__hadd2(q1[i], bh1[i]), z2));
                p0 = fmaf(f.x, w2b[2 * i], fmaf(f.y, w2b[2 * i + 1], p0));
                f = __half22float2(__hmax2(__hadd2(r0[i], bh0[i]), z2));
                p1 = fmaf(f.x, w2a[2 * i], fmaf(f.y, w2a[2 * i + 1], p1));
                f = __half22float2(__hmax2(__hadd2(r1[i], bh1[i]), z2));
                p1 = fmaf(f.x, w2b[2 * i], fmaf(f.y, w2b[2 * i + 1], p1));
            }
        }
        // two interleaved 3-step subgroup reductions
#pragma unroll
        for (int o = 4; o > 0; o >>= 1) {
            p0 += __shfl_xor_sync(0xFFFFFFFFu, p0, o);
            p1 += __shfl_xor_sync(0xFFFFFFFFu, p1, o);
        }
        if (sub == 0) {
            if (v0) { float ev = __expf(p0 + b2v); gEsort[e0] = ev; denom_part += ev; }
            if (v1) { float ev = __expf(p1 + b2v); gEsort[e1] = ev; denom_part += ev; }
        }
        s0 = sn0; s1 = sn1;
    }

    // total denom over the warp (only sub==0 lanes carry partials)
#pragma unroll
    for (int o = 16; o > 0; o >>= 1)
        denom_part += __shfl_xor_sync(0xFFFFFFFFu, denom_part, o);
    const float inv = 1.0f / denom_part;

    // pass 2: alpha + weighted sum, coalesced over the node's segment
    float sum = 0.0f;
    for (int i = start + lane; i < end; i += 32) {
        int2  rec = gSortedE[i];
        float a   = gEsort[i] * inv;
        alpha_out[rec.y] = a;
        sum += __ldg(&y[rec.x]) * a;
    }
#pragma unroll
    for (int o = 16; o > 0; o >>= 1)
        sum += __shfl_xor_sync(0xFFFFFFFFu, sum, o);
    if (lane == 0) yhat[node] = sum;
}

// ---------------------------------------------------------------------------
extern "C" void kernel_launch(void* const* d_in, const int* in_sizes, int n_in,
                              void* d_out, int out_size) {
    const float* x  = (const float*)d_in[0];
    const float* y  = (const float*)d_in[1];
    const int*   ei = (const int*)  d_in[2];
    const float* w1 = (const float*)d_in[3];
    const float* b1 = (const float*)d_in[4];
    const float* w2 = (const float*)d_in[5];
    const float* b2 = (const float*)d_in[6];

    const int N = in_sizes[1];        // y has N elements
    const int E = in_sizes[2] / 2;    // edge_index is [2, E]

    float* yhat  = (float*)d_out;         // first N elements
    float* alpha = (float*)d_out + N;     // next E elements

    const int* src = ei;
    const int* dst = ei + E;

    const int scanBlocks = (N + 255) / 256;   // 196 <= 256

    // zero histogram via async memset (capturable, no extra kernel)
    void* cntPtr = nullptr;
    cudaGetSymbolAddress(&cntPtr, gCnt);
    cudaMemsetAsync(cntPtr, 0, N * sizeof(int));

    precompute_ab<<<(N + TR - 1) / TR, 256>>>(x, w1, b1, N);
    hist_kernel<<<(E / 4 + 255) / 256, 256>>>(dst, E);
    scan_onepass<<<scanBlocks, 256>>>(N, E);
    scatter_kernel<<<(E / 4 + 255) / 256, 256>>>(src, dst, E);
    fused_node<<<(N + 7) / 8, 256>>>(y, w2, b2, alpha, yhat, N);
}

// round 15
// speedup vs baseline: 1.4938x; 1.0356x over previous
#include <cuda_runtime.h>
#include <cuda_fp16.h>

// Problem constants (fixed by the dataset)
#define NMAX 50048
#define EMAX 1600000
#define WDIM 64
#define HDIM 128

// Scratch (allocation-free rule: __device__ globals)
__device__ __half gA[NMAX * HDIM];     // x @ w1[0:64,:]  + b1
__device__ __half gB[NMAX * HDIM];     // x @ w1[64:128,:]
__device__ int    gCnt[NMAX];          // per-dst edge count (self-cleaning:
                                       // zero at load; fused_node re-zeros)
__device__ int    gOff[NMAX + 1];      // exclusive prefix (bin starts)
__device__ int    gCursor[NMAX];       // scatter cursors
__device__ int2   gSortedE[EMAX];      // {src, orig_e} grouped by dst
__device__ float  gEsort[EMAX];        // exp(logit) in sorted order
// decoupled-lookback scan state (flags reset by hist blocks each call)
__device__ volatile int gBlockSum[256];
__device__ volatile int gBlockFlag[256];

#define TR 16
#define HIST_BLOCKS 1024

// ---------------------------------------------------------------------------
// Kernel 1 (combined): blocks [0, Pblocks) run the A/B precompute GEMM;
// blocks [Pblocks, Pblocks+HIST_BLOCKS) run the dst histogram concurrently.
// The two jobs touch disjoint data, so they overlap on the chip instead of
// serializing as two launches.
// ---------------------------------------------------------------------------
__global__ void precompute_and_hist(const float* __restrict__ x,
                                    const float* __restrict__ w1,
                                    const float* __restrict__ b1,
                                    const int* __restrict__ dst,
                                    int N, int E, int Pblocks) {
    if (blockIdx.x < Pblocks) {
        // ---- precompute role ----
        __shared__ float xs[TR][WDIM];
        const int row0 = blockIdx.x * TR;
        const int tid  = threadIdx.x;

        for (int i = tid; i < TR * WDIM; i += 256) {
            int r = i >> 6, k = i & 63;
            int gr = row0 + r;
            xs[r][k] = (gr < N) ? x[gr * WDIM + k] : 0.0f;
        }
        __syncthreads();

        const int col  = tid & 127;
        const int half = tid >> 7;   // 0 -> A, 1 -> B
        const float* wbase = w1 + half * WDIM * HDIM + col;

        float acc[TR];
#pragma unroll
        for (int r = 0; r < TR; r++) acc[r] = 0.0f;

#pragma unroll 8
        for (int k = 0; k < WDIM; k++) {
            float w = __ldg(wbase + k * HDIM);
#pragma unroll
            for (int r = 0; r < TR; r++) acc[r] += xs[r][k] * w;
        }

        const float bias = (half == 0) ? __ldg(&b1[col]) : 0.0f;
        __half* out = (half == 0) ? gA : gB;
#pragma unroll
        for (int r = 0; r < TR; r++) {
            int gr = row0 + r;
            if (gr < N) out[gr * HDIM + col] = __float2half_rn(acc[r] + bias);
        }
    } else {
        // ---- histogram role (grid-stride, 4 edges per thread step) ----
        const int hb = blockIdx.x - Pblocks;
        if (hb == 0 && threadIdx.x < 256) gBlockFlag[threadIdx.x] = 0;

        const int nquads  = E >> 2;                  // full int4 groups
        const int hstride = HIST_BLOCKS * 256;
        for (int t = hb * 256 + threadIdx.x; t < nquads; t += hstride) {
            int4 d4 = reinterpret_cast<const int4*>(dst)[t];
            atomicAdd(&gCnt[d4.x], 1);
            atomicAdd(&gCnt[d4.y], 1);
            atomicAdd(&gCnt[d4.z], 1);
            atomicAdd(&gCnt[d4.w], 1);
        }
        if (hb == 0 && threadIdx.x < (E & 3)) {
            atomicAdd(&gCnt[dst[(nquads << 2) + threadIdx.x]], 1);
        }
    }
}

// ---------------------------------------------------------------------------
// Kernel 2: single-pass scan, parallel lookback. 196 blocks, co-resident.
// ---------------------------------------------------------------------------
__global__ void scan_onepass(int N, int E) {
    __shared__ int sh[256];
    __shared__ int pre[256];
    const int bid = blockIdx.x;
    const int tid = threadIdx.x;
    const int idx = bid * 256 + tid;

    int v = (idx < N) ? gCnt[idx] : 0;
    sh[tid] = v;
    __syncthreads();
#pragma unroll
    for (int o = 1; o < 256; o <<= 1) {
        int t = (tid >= o) ? sh[tid - o] : 0;
        __syncthreads();
        sh[tid] += t;
        __syncthreads();
    }
    const int incl = sh[tid];          // inclusive within block

    if (tid == 255) {                  // publish block aggregate
        gBlockSum[bid] = incl;
        __threadfence();
        gBlockFlag[bid] = 1;
    }
    // parallel lookback: lane t grabs predecessor t's aggregate
    int contrib = 0;
    if (tid < bid) {
        while (gBlockFlag[tid] == 0) { }
        contrib = gBlockSum[tid];
    }
    pre[tid] = contrib;
    __syncthreads();
    for (int o = 128; o > 0; o >>= 1) {
        if (tid < o) pre[tid] += pre[tid + o];
        __syncthreads();
    }
    const int excl = pre[0] + incl - v;
    if (idx < N) {
        gOff[idx]    = excl;
        gCursor[idx] = excl;
        if (idx == N - 1) gOff[N] = excl + v;   // == E
    }
}

// ---------------------------------------------------------------------------
// Kernel 3: scatter edges into dst-grouped order (4 edges/thread)
// ---------------------------------------------------------------------------
__global__ void scatter_kernel(const int* __restrict__ src,
                               const int* __restrict__ dst, int E) {
    int t = blockIdx.x * blockDim.x + threadIdx.x;
    int e0 = t * 4;
    if (e0 + 3 < E) {
        int4 s4 = reinterpret_cast<const int4*>(src)[t];
        int4 d4 = reinterpret_cast<const int4*>(dst)[t];
        int p0 = atomicAdd(&gCursor[d4.x], 1);
        int p1 = atomicAdd(&gCursor[d4.y], 1);
        int p2 = atomicAdd(&gCursor[d4.z], 1);
        int p3 = atomicAdd(&gCursor[d4.w], 1);
        gSortedE[p0] = make_int2(s4.x, e0);
        gSortedE[p1] = make_int2(s4.y, e0 + 1);
        gSortedE[p2] = make_int2(s4.z, e0 + 2);
        gSortedE[p3] = make_int2(s4.w, e0 + 3);
    } else {
        for (int e = e0; e < E; e++) {
            int pos = atomicAdd(&gCursor[dst[e]], 1);
            gSortedE[pos] = make_int2(src[e], e);
        }
    }
}

// ---------------------------------------------------------------------------
// Kernel 4: FUSED per-node kernel — warp per node, no atomics.
// 8 lanes/edge, contiguous addressing, record prefetch pipeline.
// Also SELF-CLEANS gCnt[node]=0 so the next run needs no memset.
// ---------------------------------------------------------------------------
__global__ void __launch_bounds__(256, 3) fused_node(
        const float* __restrict__ y,
        const float* __restrict__ w2,
        const float* __restrict__ b2,
        float* __restrict__ alpha_out,
        float* __restrict__ yhat, int N) {
    const int lane = threadIdx.x & 31;
    const int sub  = lane & 7;          // lane within 8-group
    const int g    = lane >> 3;         // subgroup 0..3
    const int node = blockIdx.x * (blockDim.x >> 5) + (threadIdx.x >> 5);
    if (node >= N) return;

    if (lane == 0) gCnt[node] = 0;      // self-clean for the next run

    const int start = gOff[node];
    const int end   = gOff[node + 1];

    const uint4* A4 = reinterpret_cast<const uint4*>(gA);  // 16 uint4 / row
    const uint4* B4 = reinterpret_cast<const uint4*>(gB);

    // B[node]: lane sub holds halves [8*sub, 8*sub+8) and [64+8*sub, ...+8)
    uint4 br0 = B4[node * 16 + sub];
    uint4 br1 = B4[node * 16 + 8 + sub];
    __half2 bh0[4], bh1[4];
    {
        const __half2* p0 = reinterpret_cast<const __half2*>(&br0);
        const __half2* p1 = reinterpret_cast<const __half2*>(&br1);
#pragma unroll
        for (int i = 0; i < 4; i++) { bh0[i] = p0[i]; bh1[i] = p1[i]; }
    }

    // w2 coefficients matching the halves above
    float w2a[8], w2b[8];
#pragma unroll
    for (int i = 0; i < 2; i++) {
        float4 ta = reinterpret_cast<const float4*>(w2)[sub * 2 + i];
        float4 tb = reinterpret_cast<const float4*>(w2)[16 + sub * 2 + i];
        w2a[4 * i] = ta.x; w2a[4 * i + 1] = ta.y; w2a[4 * i + 2] = ta.z; w2a[4 * i + 3] = ta.w;
        w2b[4 * i] = tb.x; w2b[4 * i + 1] = tb.y; w2b[4 * i + 2] = tb.z; w2b[4 * i + 3] = tb.w;
    }
    const float  b2v = __ldg(b2);
    const __half2 z2 = __float2half2_rn(0.0f);

    float denom_part = 0.0f;

    // prologue: records for the first batch
    int s0 = (start + g     < end) ? gSortedE[start + g].x     : 0;
    int s1 = (start + g + 4 < end) ? gSortedE[start + g + 4].x : 0;

    for (int base = start; base < end; base += 8) {
        const int e0 = base + g, e1 = base + g + 4;
        const bool v0 = e0 < end, v1 = e1 < end;

        // prefetch next batch's records (overlaps A-gather + compute below)
        const int n0 = e0 + 8, n1 = e1 + 8;
        const int sn0 = (n0 < end) ? gSortedE[n0].x : 0;
        const int sn1 = (n1 < end) ? gSortedE[n1].x : 0;

        // 4 independent, fully-coalesced gathers issued before any use
        uint4 a00 = A4[s0 * 16 + sub];
        uint4 a01 = A4[s0 * 16 + 8 + sub];
        uint4 a10 = A4[s1 * 16 + sub];
        uint4 a11 = A4[s1 * 16 + 8 + sub];

        float p0 = 0.0f, p1 = 0.0f;
        {
            const __half2* q0 = reinterpret_cast<const __half2*>(&a00);
            const __half2* q1 = reinterpret_cast<const __half2*>(&a01);
            const __half2* r0 = reinterpret_cast<const __half2*>(&a10);
            const __half2* r1 = reinterpret_cast<const __half2*>(&a11);
#pragma unroll
            for (int i = 0; i < 4; i++) {
                float2 f;
                f = __half22float2(__hmax2(__hadd2(q0[i], bh0[i]), z2));
                p0 = fmaf(f.x, w2a[2 * i], fmaf(f.y, w2a[2 * i + 1], p0));
                f = __half22float2(__hmax2(__hadd2(q1[i], bh1[i]), z2));
                p0 = fmaf(f.x, w2b[2 * i], fmaf(f.y, w2b[2 * i + 1], p0));
                f = __half22float2(__hmax2(__hadd2(r0[i], bh0[i]), z2));
                p1 = fmaf(f.x, w2a[2 * i], fmaf(f.y, w2a[2 * i + 1], p1));
                f = __half22float2(__hmax2(__hadd2(r1[i], bh1[i]), z2));
                p1 = fmaf(f.x, w2b[2 * i], fmaf(f.y, w2b[2 * i + 1], p1));
            }
        }
        // two interleaved 3-step subgroup reductions
#pragma unroll
        for (int o = 4; o > 0; o >>= 1) {
            p0 += __shfl_xor_sync(0xFFFFFFFFu, p0, o);
            p1 += __shfl_xor_sync(0xFFFFFFFFu, p1, o);
        }
        if (sub == 0) {
            if (v0) { float ev = __expf(p0 + b2v); gEsort[e0] = ev; denom_part += ev; }
            if (v1) { float ev = __expf(p1 + b2v); gEsort[e1] = ev; denom_part += ev; }
        }
        s0 = sn0; s1 = sn1;
    }

    // total denom over the warp (only sub==0 lanes carry partials)
#pragma unroll
    for (int o = 16; o > 0; o >>= 1)
        denom_part += __shfl_xor_sync(0xFFFFFFFFu, denom_part, o);
    const float inv = 1.0f / denom_part;

    // pass 2: alpha + weighted sum, coalesced over the node's segment
    float sum = 0.0f;
    for (int i = start + lane; i < end; i += 32) {
        int2  rec = gSortedE[i];
        float a   = gEsort[i] * inv;
        alpha_out[rec.y] = a;
        sum += __ldg(&y[rec.x]) * a;
    }
#pragma unroll
    for (int o = 16; o > 0; o >>= 1)
        sum += __shfl_xor_sync(0xFFFFFFFFu, sum, o);
    if (lane == 0) yhat[node] = sum;
}

// ---------------------------------------------------------------------------
extern "C" void kernel_launch(void* const* d_in, const int* in_sizes, int n_in,
                              void* d_out, int out_size) {
    const float* x  = (const float*)d_in[0];
    const float* y  = (const float*)d_in[1];
    const int*   ei = (const int*)  d_in[2];
    const float* w1 = (const float*)d_in[3];
    const float* b1 = (const float*)d_in[4];
    const float* w2 = (const float*)d_in[5];
    const float* b2 = (const float*)d_in[6];

    const int N = in_sizes[1];        // y has N elements
    const int E = in_sizes[2] / 2;    // edge_index is [2, E]

    float* yhat  = (float*)d_out;         // first N elements
    float* alpha = (float*)d_out + N;     // next E elements

    const int* src = ei;
    const int* dst = ei + E;

    const int Pblocks    = (N + TR - 1) / TR;   // precompute blocks
    const int scanBlocks = (N + 255) / 256;     // 196 <= 256

    precompute_and_hist<<<Pblocks + HIST_BLOCKS, 256>>>(x, w1, b1, dst,
                                                        N, E, Pblocks);
    scan_onepass<<<scanBlocks, 256>>>(N, E);
    scatter_kernel<<<(E / 4 + 255) / 256, 256>>>(src, dst, E);
    fused_node<<<(N + 7) / 8, 256>>>(y, w2, b2, alpha, yhat, N);
}